// round 1
// baseline (speedup 1.0000x reference)
#include <cuda_runtime.h>
#include <math.h>

// Problem constants
#define Bsz   4
#define Csz   16
#define Tsz   32
#define Hsz   128
#define Wsz   128
#define Klow  4
#define TAU   0.1f
#define EPS2  1e-12f          // (1e-6)^2

#define HW        (Hsz * Wsz)          // 16384
#define HW4       (HW / 4)             // 4096
#define NLOC      (Bsz * Csz * HW)     // 1,048,576 spatial locations
#define NTHREADS  (NLOC / 4)           // 262,144 threads (4 loc per thread via float4)
#define BLOCK     256
#define NBLOCKS   (NTHREADS / BLOCK)   // 1024

#define N_MAIN  ((double)Bsz * Csz * Tsz * HW)          // 33,554,432
#define N_TEMP  ((double)Bsz * Csz * (Tsz - 1) * HW)    // 32,505,856

// Per-block partials: [0..NBLOCKS) charbonnier sums, [NBLOCKS..2*NBLOCKS) temp sums
__device__ float g_partials[2 * NBLOCKS];

__global__ void __launch_bounds__(BLOCK)
loss_pass1(const float4* __restrict__ X, const float4* __restrict__ Y)
{
    __shared__ float sD[Klow][Tsz];   // orthonormal DCT rows 0..3
    __shared__ float sG[Klow * Klow]; // G = E E^T, E[n,s] = D[n,s+1]-D[n,s]
    __shared__ float red[2][BLOCK];

    const int tid = threadIdx.x;

    // Build D (4x32) — 128 threads, one entry each
    if (tid < Klow * Tsz) {
        int n = tid >> 5;
        int t = tid & 31;
        float v = sqrtf(2.0f / (float)Tsz) *
                  cosf((float)M_PI * (2.0f * t + 1.0f) * (float)n / (2.0f * (float)Tsz));
        if (n == 0) v *= 0.7071067811865476f;
        sD[n][t] = v;
    }
    __syncthreads();
    // Build G (4x4) — 16 threads
    if (tid < Klow * Klow) {
        int n = tid >> 2;
        int m = tid & 3;
        float g = 0.0f;
        #pragma unroll
        for (int s = 0; s < Tsz - 1; s++) {
            float en = sD[n][s + 1] - sD[n][s];
            float em = sD[m][s + 1] - sD[m][s];
            g += en * em;
        }
        sG[tid] = g;
    }
    __syncthreads();

    // Each thread: 4 consecutive spatial locations (one float4 column through T)
    const unsigned i   = blockIdx.x * BLOCK + tid;
    const unsigned hw4 = i & (HW4 - 1);
    const unsigned bc  = i >> 12;               // i / HW4
    const size_t base  = (size_t)bc * (Tsz * HW4) + hw4;

    float charb = 0.0f;
    float c0x = 0.f, c0y = 0.f, c0z = 0.f, c0w = 0.f;
    float c1x = 0.f, c1y = 0.f, c1z = 0.f, c1w = 0.f;
    float c2x = 0.f, c2y = 0.f, c2z = 0.f, c2w = 0.f;
    float c3x = 0.f, c3y = 0.f, c3z = 0.f, c3w = 0.f;

    #pragma unroll 4
    for (int t = 0; t < Tsz; t++) {
        float4 a = X[base + (size_t)t * HW4];
        float4 b = Y[base + (size_t)t * HW4];
        float dx = a.x - b.x, dy = a.y - b.y, dz = a.z - b.z, dw = a.w - b.w;

        charb += sqrtf(dx * dx + EPS2) + sqrtf(dy * dy + EPS2)
               + sqrtf(dz * dz + EPS2) + sqrtf(dw * dw + EPS2);

        float w0 = sD[0][t], w1 = sD[1][t], w2 = sD[2][t], w3 = sD[3][t];
        c0x += dx * w0; c0y += dy * w0; c0z += dz * w0; c0w += dw * w0;
        c1x += dx * w1; c1y += dy * w1; c1z += dz * w1; c1w += dw * w1;
        c2x += dx * w2; c2y += dy * w2; c2z += dz * w2; c2w += dw * w2;
        c3x += dx * w3; c3y += dy * w3; c3z += dz * w3; c3w += dw * w3;
    }

    // temp contribution: sum over 4 lanes of c^T G c
    float temp = 0.0f;
    {
        float cl[4][4] = {{c0x, c1x, c2x, c3x},
                          {c0y, c1y, c2y, c3y},
                          {c0z, c1z, c2z, c3z},
                          {c0w, c1w, c2w, c3w}};
        #pragma unroll
        for (int l = 0; l < 4; l++) {
            #pragma unroll
            for (int n = 0; n < Klow; n++) {
                float acc = 0.0f;
                #pragma unroll
                for (int m = 0; m < Klow; m++)
                    acc += cl[l][m] * sG[n * Klow + m];
                temp += cl[l][n] * acc;
            }
        }
    }

    // Deterministic block reduction
    red[0][tid] = charb;
    red[1][tid] = temp;
    __syncthreads();
    for (int s = BLOCK / 2; s > 0; s >>= 1) {
        if (tid < s) {
            red[0][tid] += red[0][tid + s];
            red[1][tid] += red[1][tid + s];
        }
        __syncthreads();
    }
    if (tid == 0) {
        g_partials[blockIdx.x]           = red[0][0];
        g_partials[NBLOCKS + blockIdx.x] = red[1][0];
    }
}

__global__ void __launch_bounds__(BLOCK)
loss_pass2(float* __restrict__ out)
{
    __shared__ double r0[BLOCK];
    __shared__ double r1[BLOCK];
    const int tid = threadIdx.x;

    double s0 = 0.0, s1 = 0.0;
    for (int i = tid; i < NBLOCKS; i += BLOCK) {
        s0 += (double)g_partials[i];
        s1 += (double)g_partials[NBLOCKS + i];
    }
    r0[tid] = s0;
    r1[tid] = s1;
    __syncthreads();
    for (int s = BLOCK / 2; s > 0; s >>= 1) {
        if (tid < s) {
            r0[tid] += r0[tid + s];
            r1[tid] += r1[tid + s];
        }
        __syncthreads();
    }
    if (tid == 0) {
        double L_main = r0[0] / N_MAIN;
        double L_temp = r1[0] / N_TEMP;
        double total  = L_main + (double)TAU * L_temp;
        out[0] = (float)total;
        out[1] = (float)L_main;
        out[2] = (float)L_temp;
    }
}

extern "C" void kernel_launch(void* const* d_in, const int* in_sizes, int n_in,
                              void* d_out, int out_size)
{
    const float4* X = (const float4*)d_in[0];
    const float4* Y = (const float4*)d_in[1];
    float* out = (float*)d_out;

    loss_pass1<<<NBLOCKS, BLOCK>>>(X, Y);
    loss_pass2<<<1, BLOCK>>>(out);
}